// round 16
// baseline (speedup 1.0000x reference)
#include <cuda_runtime.h>
#include <math.h>

#define NN    256
#define FEATD 1024
#define HIDR  256
#define HEADS 4
#define GCH   256
#define H1DIM 1024   // HEADS*GCH
#define OUTD  21
#define TOPK  3
#define E_TOT (NN*TOPK + NN)   // 1024 edges

// ---------------- scratch (device globals; no allocation allowed) ----------
__device__ __align__(16) float g_A[NN*HIDR];
__device__ __align__(16) float g_B[NN*HIDR];
__device__ __align__(16) float g_rel[NN*NN];
__device__ int   g_off[NN+1];
__device__ int   g_inc[E_TOT];
__device__ __align__(16) float g_h1[NN*H1DIM];
__device__ float g_ss1[NN*HEADS], g_ds1[NN*HEADS];
__device__ __align__(16) float g_x1[NN*H1DIM];
__device__ __align__(16) float g_h2[NN*OUTD];
__device__ float g_ss2[NN], g_ds2[NN];
__device__ __align__(16) float g_W2T[OUTD*H1DIM];   // W2 transposed [o][c]

// edge id -> source node (edges 0..767 are topk from row e/3; 768.. are loops)
__device__ __forceinline__ int edge_src(int e) {
    return (e < NN * TOPK) ? (e / TOPK) : (e - NN * TOPK);
}

// read a scalar that may have been serialized as int32 or float32
__device__ __forceinline__ float read_dim(const void* p) {
    int iv = *(const int*)p;
    if (iv > 0 && iv < 100000) return (float)iv;
    return *(const float*)p;
}

// ---------------- K1: combined GEMMs -----------------------------------
// Tile BM=16, BN=64, 2-way split-K, 256 threads, 384 blocks (fine-grained
// for wave balance; ~5 warps/SMSP so FFMA issue is the binding constraint).
// colt 0..7   -> [g_A|g_B] = F @ W_fc1[0:2048] (cols 0..511)
// colt 8..23  -> g_h1 = [F|geomn] @ W1         (cols 0..1023)
__global__ __launch_bounds__(256)
void k_mm(const float* __restrict__ feat, const float* __restrict__ Wfc1,
          const float* __restrict__ W1, const float* __restrict__ boxes,
          const void* img_h, const void* img_w) {
    __shared__ float sAT[2][16][20];
    __shared__ float sW[2][16][64];
    __shared__ float sRed[128][9];
    int b = blockIdx.x;
    int t = threadIdx.x;
    int half = t >> 7, ht = t & 127;
    int tx = ht & 15, ty = ht >> 4;          // ty 0..7 -> rows ty, ty+8
    int rowt = b & 15, colt = b >> 4;
    int row0 = rowt * 16;
    int col0g = colt * 64;

    const float* W;
    float* dst;
    int colL, ldw;
    bool gemm1 = (col0g >= 512);
    if (!gemm1) {
        ldw = HIDR;
        if (col0g < 256) { W = Wfc1;                       dst = g_A; colL = col0g; }
        else             { W = Wfc1 + (size_t)1024 * HIDR; dst = g_B; colL = col0g - 256; }
    } else {
        colL = col0g - 512;
        ldw = H1DIM;
        W = W1;
        dst = g_h1;
    }

    float (*mAT)[20] = sAT[half];
    float (*mW)[64]  = sW[half];

    int arow = (ht >> 2) & 15, akq = ht & 3;     // A loader (ht<64 active)
    int wkr  = ht >> 3,        wcq = ht & 7;     // W loader (all 128)
    int k0 = half * 512;                          // K half
    const float* Aptr = feat + (size_t)(row0 + arow) * FEATD + k0 + akq * 4;
    const float* Wptr = W + (size_t)(k0 + wkr) * ldw + colL + wcq * 8;

    float acc[2][4] = {};
    float4 pa  = *(const float4*)Aptr;
    float4 pw0 = *(const float4*)Wptr;
    float4 pw1 = *(const float4*)(Wptr + 4);
#pragma unroll 1
    for (int kt = 0; kt < 32; kt++) {
        if (ht < 64) {
            mAT[akq*4+0][arow] = pa.x;
            mAT[akq*4+1][arow] = pa.y;
            mAT[akq*4+2][arow] = pa.z;
            mAT[akq*4+3][arow] = pa.w;
        }
        *(float4*)&mW[wkr][wcq*8]     = pw0;
        *(float4*)&mW[wkr][wcq*8 + 4] = pw1;
        __syncthreads();
        if (kt + 1 < 32) {
            const float* An = Aptr + (kt + 1) * 16;
            const float* Wn = Wptr + (size_t)(kt + 1) * 16 * ldw;
            pa  = *(const float4*)An;
            pw0 = *(const float4*)Wn;
            pw1 = *(const float4*)(Wn + 4);
        }
#pragma unroll
        for (int kk = 0; kk < 16; kk++) {
            float a0 = mAT[kk][ty], a1 = mAT[kk][ty + 8];
            float4 w = *(const float4*)&mW[kk][tx*4];
            acc[0][0] += a0 * w.x; acc[0][1] += a0 * w.y; acc[0][2] += a0 * w.z; acc[0][3] += a0 * w.w;
            acc[1][0] += a1 * w.x; acc[1][1] += a1 * w.y; acc[1][2] += a1 * w.z; acc[1][3] += a1 * w.w;
        }
        __syncthreads();
    }

    // reduce the two K-halves
    if (half == 1) {
#pragma unroll
        for (int u = 0; u < 2; u++)
#pragma unroll
            for (int j = 0; j < 4; j++)
                sRed[ht][u * 4 + j] = acc[u][j];
    }
    __syncthreads();
    if (half == 0) {
#pragma unroll
        for (int u = 0; u < 2; u++)
#pragma unroll
            for (int j = 0; j < 4; j++)
                acc[u][j] += sRed[ht][u * 4 + j];
        if (gemm1) {
            float fw = read_dim(img_w), fh = read_dim(img_h);
#pragma unroll
            for (int u = 0; u < 2; u++) {
                int n = row0 + ty + u * 8;
                float b0 = boxes[n*4+0] / fw, b1 = boxes[n*4+1] / fh;
                float b2 = boxes[n*4+2] / fw, b3 = boxes[n*4+3] / fh;
                float G[4] = { b0, b1, b2 - b0, b3 - b1 };
#pragma unroll
                for (int kk = 0; kk < 4; kk++) {
                    float4 w = *(const float4*)&W1[(size_t)(FEATD + kk) * H1DIM + colL + tx*4];
                    acc[u][0] += G[kk] * w.x;
                    acc[u][1] += G[kk] * w.y;
                    acc[u][2] += G[kk] * w.z;
                    acc[u][3] += G[kk] * w.w;
                }
            }
        }
#pragma unroll
        for (int u = 0; u < 2; u++) {
            int r = row0 + ty + u * 8;
            *(float4*)&dst[(size_t)r * ldw + colL + tx*4] =
                make_float4(acc[u][0], acc[u][1], acc[u][2], acc[u][3]);
        }
    }
}

// ---------------- K2: rel[i,j] = relu(A[i]+B[j]+bias+geom@Wg) . W_fc2 + b2 -
// 256 threads (2 warps/SMSP -> FFMA-saturating). Thread = 1 i x 2 j.
__global__ __launch_bounds__(256)
void k_rel(const float* __restrict__ boxes,
           const float* __restrict__ Wfc1,
           const float* __restrict__ bfc1,
           const float* __restrict__ Wfc2,
           const float* __restrict__ bfc2) {
    __shared__ __align__(16) float sAb[8][HIDR];
    __shared__ __align__(16) float sBt[HIDR][68];
    __shared__ __align__(16) float4 sGeo[HIDR];
    __shared__ float sW2[HIDR];
    int t = threadIdx.x;                 // 256
    int il = t >> 5, lane = t & 31, jl = lane * 2;
    int i0 = blockIdx.y * 8, j0 = blockIdx.x * 64;
    const float* Wg = Wfc1 + (size_t)2 * FEATD * HIDR;
    for (int idx = t; idx < 8 * HIDR; idx += 256) {
        int i = idx >> 8, c = idx & 255;
        sAb[i][c] = g_A[(size_t)(i0 + i) * HIDR + c] + bfc1[c];
    }
    for (int idx = t; idx < 64 * HIDR; idx += 256) {
        int j = idx >> 8, c = idx & 255;
        sBt[c][j] = g_B[(size_t)(j0 + j) * HIDR + c];
    }
    for (int c = t; c < HIDR; c += 256) {
        sGeo[c] = make_float4(Wg[c], Wg[HIDR + c], Wg[2 * HIDR + c], Wg[3 * HIDR + c]);
        sW2[c] = Wfc2[c];
    }
    __syncthreads();
    int ig = i0 + il;
    float bi0 = boxes[ig*4+0], bi1 = boxes[ig*4+1], bi2 = boxes[ig*4+2], bi3 = boxes[ig*4+3];
    float4 G0, G1;
    {
        int ja = j0 + jl, jb = ja + 1;
        G0 = make_float4(fabsf(bi0 - boxes[ja*4+0]), fabsf(bi1 - boxes[ja*4+1]),
                         fabsf(bi2 - boxes[ja*4+2]), fabsf(bi3 - boxes[ja*4+3]));
        G1 = make_float4(fabsf(bi0 - boxes[jb*4+0]), fabsf(bi1 - boxes[jb*4+1]),
                         fabsf(bi2 - boxes[jb*4+2]), fabsf(bi3 - boxes[jb*4+3]));
    }
    float acc0 = 0.f, acc1 = 0.f;
#pragma unroll 4
    for (int c = 0; c < HIDR; c++) {
        float  a  = sAb[il][c];
        float4 wg = sGeo[c];
        float  w2 = sW2[c];
        float2 bv = *(const float2*)&sBt[c][jl];
        float v0 = a + bv.x + G0.x*wg.x + G0.y*wg.y + G0.z*wg.z + G0.w*wg.w;
        float v1 = a + bv.y + G1.x*wg.x + G1.y*wg.y + G1.z*wg.z + G1.w*wg.w;
        acc0 += fmaxf(v0, 0.f) * w2;
        acc1 += fmaxf(v1, 0.f) * w2;
    }
    float bb = bfc2[0];
    g_rel[(size_t)ig * NN + j0 + jl]     = acc0 + bb;
    g_rel[(size_t)ig * NN + j0 + jl + 1] = acc1 + bb;
}

// ---------------- K3: block 0 = topk + CSR + W2T; blocks 1..32 = score1 ----
__global__ void k_topk_score(const float* __restrict__ W2,
                             const float* __restrict__ a_src,
                             const float* __restrict__ a_dst) {
    int t = threadIdx.x;                 // 1024
    int lane = t & 31, w = t >> 5;
    if (blockIdx.x > 0) {
        // ---- score1: 8 nodes per block, 128 threads per node ----
        int n = (blockIdx.x - 1) * 8 + (t >> 7);
        int wt = t & 127;
        int hd = wt >> 5;
        float s = 0.f, d = 0.f;
        const float* hr = &g_h1[(size_t)n * H1DIM + hd * GCH];
        for (int c = lane; c < GCH; c += 32) {
            float hv = hr[c];
            s += hv * a_src[hd * GCH + c];
            d += hv * a_dst[hd * GCH + c];
        }
#pragma unroll
        for (int o = 16; o; o >>= 1) {
            s += __shfl_down_sync(0xffffffffu, s, o);
            d += __shfl_down_sync(0xffffffffu, d, o);
        }
        if (!lane) { g_ss1[n * HEADS + hd] = s; g_ds1[n * HEADS + hd] = d; }
        return;
    }
    // ---- block 0: topk + CSR + W2T ----
    __shared__ int sTop[NN * TOPK];
    __shared__ int M[32][NN];
    __shared__ int off[NN];
    for (int idx = t; idx < 32 * NN; idx += 1024) ((int*)M)[idx] = 0;
    for (int i = w; i < NN; i += 32) {
        float v[8];
#pragma unroll
        for (int q = 0; q < 8; q++) v[q] = g_rel[i * NN + q * 32 + lane];
#pragma unroll
        for (int sel = 0; sel < TOPK + 1; sel++) {
            float bv = -INFINITY; int bi = 0;
#pragma unroll
            for (int q = 0; q < 8; q++) {
                int idx = q * 32 + lane;
                if (v[q] > bv) { bv = v[q]; bi = idx; }
            }
#pragma unroll
            for (int o = 16; o; o >>= 1) {
                float ov = __shfl_down_sync(0xffffffffu, bv, o);
                int   oi = __shfl_down_sync(0xffffffffu, bi, o);
                if (ov > bv || (ov == bv && oi < bi)) { bv = ov; bi = oi; }
            }
            bi = __shfl_sync(0xffffffffu, bi, 0);
            if (sel > 0 && lane == 0) sTop[i * TOPK + sel - 1] = bi;
            if ((bi & 31) == lane) v[bi >> 5] = -INFINITY;
        }
    }
    for (int idx = t; idx < OUTD * H1DIM; idx += 1024) {
        int o = idx / H1DIM, c = idx - o * H1DIM;
        g_W2T[idx] = W2[c * OUTD + o];
    }
    __syncthreads();
    int e = t;
    int tg = (e < NN * TOPK) ? sTop[e] : (e - NN * TOPK);
    unsigned same = __match_any_sync(0xffffffffu, tg);
    int rank = __popc(same & ((1u << lane) - 1u));
    if (rank == 0) M[w][tg] = __popc(same);
    __syncthreads();
    if (t < NN) {
        int run = 0;
#pragma unroll
        for (int cc = 0; cc < 32; cc++) { int v = M[cc][t]; M[cc][t] = run; run += v; }
        off[t] = run;
    }
    __syncthreads();
    for (int s = 1; s < NN; s <<= 1) {
        int v = 0;
        if (t < NN && t >= s) v = off[t - s];
        __syncthreads();
        if (t < NN) off[t] += v;
        __syncthreads();
    }
    if (t < NN) {
        g_off[t + 1] = off[t];
        if (t == 0) g_off[0] = 0;
    }
    __syncthreads();
    int base = (tg == 0) ? 0 : off[tg - 1];
    g_inc[base + M[w][tg] + rank] = e;
}

// ---------------- K4: GAT1 aggregation, one block per (node, head) ---------
// Hub node's 1MB gather is split across 4 SMs (one per head).
__global__ __launch_bounds__(128)
void k_gat1h(const float* __restrict__ b1) {
    int n = blockIdx.x, hd = blockIdx.y;
    int t = threadIdx.x;                 // 128
    int off = g_off[n], cnt = g_off[n + 1] - off;
    __shared__ int   sSrc[E_TOT];
    __shared__ float alh[E_TOT];
    __shared__ float red[2];
    __shared__ __align__(16) float sXp[GCH];   // slice-1 partials
    float ds1n = g_ds1[n * HEADS + hd];
    for (int k = t; k < cnt; k += 128) {
        int sn = edge_src(g_inc[off + k]);
        sSrc[k] = sn;
        float x = g_ss1[sn * HEADS + hd] + ds1n;
        alh[k] = (x >= 0.f) ? x : 0.2f * x;    // leaky_relu 0.2
    }
    __syncthreads();
    if (t < 32) {
        float m = -INFINITY;
        for (int k = t; k < cnt; k += 32) m = fmaxf(m, alh[k]);
#pragma unroll
        for (int o = 16; o; o >>= 1) m = fmaxf(m, __shfl_xor_sync(0xffffffffu, m, o));
        float s = 0.f;
        for (int k = t; k < cnt; k += 32) s += expf(alh[k] - m);
#pragma unroll
        for (int o = 16; o; o >>= 1) s += __shfl_xor_sync(0xffffffffu, s, o);
        if (t == 0) { red[0] = m; red[1] = 1.f / s; }
    }
    __syncthreads();
    float m = red[0], inv = red[1];
    for (int k = t; k < cnt; k += 128) alh[k] = expf(alh[k] - m) * inv;
    __syncthreads();
    // aggregation: 2 edge-slices x 64 output-threads (4 outputs each)
    {
        int slice = t >> 6, ot = t & 63;
        int o4 = ot * 4;                       // within-head column
        int col = hd * GCH + o4;               // global h1 column
        float ax = 0.f, ay = 0.f, az = 0.f, aw = 0.f;
        int k = slice;
        for (; k + 6 < cnt; k += 8) {
            float a0 = alh[k+0], a1 = alh[k+2], a2 = alh[k+4], a3 = alh[k+6];
            const float4 h0 = *(const float4*)&g_h1[(size_t)sSrc[k+0] * H1DIM + col];
            const float4 h1 = *(const float4*)&g_h1[(size_t)sSrc[k+2] * H1DIM + col];
            const float4 h2 = *(const float4*)&g_h1[(size_t)sSrc[k+4] * H1DIM + col];
            const float4 h3 = *(const float4*)&g_h1[(size_t)sSrc[k+6] * H1DIM + col];
            ax += a0*h0.x + a1*h1.x + a2*h2.x + a3*h3.x;
            ay += a0*h0.y + a1*h1.y + a2*h2.y + a3*h3.y;
            az += a0*h0.z + a1*h1.z + a2*h2.z + a3*h3.z;
            aw += a0*h0.w + a1*h1.w + a2*h2.w + a3*h3.w;
        }
        for (; k < cnt; k += 2) {
            float a = alh[k];
            const float4 h = *(const float4*)&g_h1[(size_t)sSrc[k] * H1DIM + col];
            ax += a * h.x; ay += a * h.y; az += a * h.z; aw += a * h.w;
        }
        if (slice == 1) *(float4*)&sXp[o4] = make_float4(ax, ay, az, aw);
        __syncthreads();
        if (slice == 0) {
            float4 p = *(const float4*)&sXp[o4];
            float4 bb = *(const float4*)&b1[col];
            *(float4*)&g_x1[(size_t)n * H1DIM + col] = make_float4(
                fmaxf(ax + p.x + bb.x, 0.f), fmaxf(ay + p.y + bb.y, 0.f),
                fmaxf(az + p.z + bb.z, 0.f), fmaxf(aw + p.w + bb.w, 0.f));
        }
    }
}

// ---------------- K5: h2 = x1 @ W2T + layer-2 attention scores -------------
__global__ __launch_bounds__(128)
void k_g2(const float* __restrict__ a_src2, const float* __restrict__ a_dst2) {
    int n = blockIdx.x, t = threadIdx.x;   // 128 threads
    int w = t >> 5, lane = t & 31;
    __shared__ __align__(16) float sX[H1DIM];
    __shared__ float lg[OUTD];
    for (int c = t * 4; c < H1DIM; c += 512)
        *(float4*)&sX[c] = *(const float4*)&g_x1[(size_t)n * H1DIM + c];
    __syncthreads();
    for (int o = w; o < OUTD; o += 4) {
        const float* wr = &g_W2T[o * H1DIM];
        float s = 0.f;
        for (int c = lane * 4; c < H1DIM; c += 128) {
            float4 xv = *(const float4*)&sX[c];
            float4 wv = *(const float4*)&wr[c];
            s += xv.x * wv.x + xv.y * wv.y + xv.z * wv.z + xv.w * wv.w;
        }
#pragma unroll
        for (int o2 = 16; o2; o2 >>= 1) s += __shfl_down_sync(0xffffffffu, s, o2);
        if (!lane) { g_h2[n * OUTD + o] = s; lg[o] = s; }
    }
    __syncthreads();
    if (t == 0) {
        float s = 0.f, d = 0.f;
        for (int oo = 0; oo < OUTD; oo++) {
            s += lg[oo] * a_src2[oo];
            d += lg[oo] * a_dst2[oo];
        }
        g_ss2[n] = s; g_ds2[n] = d;
    }
}

// ---------------- K6: GAT2 edge-sliced aggregate -> logits + labels --------
__global__ void k_gat2(const float* __restrict__ b2, float* __restrict__ out,
                       int out_size) {
    int tnode = blockIdx.x, tid = threadIdx.x;   // 256 threads
    int off = g_off[tnode], cnt = g_off[tnode + 1] - off;
    __shared__ int   sSrc[E_TOT];
    __shared__ float al[E_TOT];
    __shared__ float red[2];            // m, inv_sum
    __shared__ float partial[8][32];
    __shared__ float lg[OUTD];
    for (int k = tid; k < cnt; k += 256) {
        int sn = edge_src(g_inc[off + k]);
        sSrc[k] = sn;
        float x = g_ss2[sn] + g_ds2[tnode];
        al[k] = (x >= 0.f) ? x : 0.2f * x;
    }
    __syncthreads();
    if (tid < 32) {
        float m = -INFINITY;
        for (int k = tid; k < cnt; k += 32) m = fmaxf(m, al[k]);
#pragma unroll
        for (int o = 16; o; o >>= 1) m = fmaxf(m, __shfl_xor_sync(0xffffffffu, m, o));
        float s = 0.f;
        for (int k = tid; k < cnt; k += 32) s += expf(al[k] - m);
#pragma unroll
        for (int o = 16; o; o >>= 1) s += __shfl_xor_sync(0xffffffffu, s, o);
        if (tid == 0) { red[0] = m; red[1] = 1.f / s; }
    }
    __syncthreads();
    float m = red[0], inv = red[1];
    for (int k = tid; k < cnt; k += 256) al[k] = expf(al[k] - m) * inv;
    __syncthreads();
    {
        int es = tid >> 5, o = tid & 31;
        if (o < OUTD) {
            float acc = 0.f;
            for (int k = es; k < cnt; k += 8)
                acc += al[k] * g_h2[sSrc[k] * OUTD + o];
            partial[es][o] = acc;
        }
    }
    __syncthreads();
    if (tid < OUTD) {
        float v = b2[tid];
#pragma unroll
        for (int es = 0; es < 8; es++) v += partial[es][tid];
        lg[tid] = v;
        out[tnode * OUTD + tid] = v;
    }
    __syncthreads();
    if (tid == 0 && out_size >= NN * OUTD + NN) {
        int best = 0;
        float bv = lg[0];
        for (int o = 1; o < OUTD; o++)
            if (lg[o] > bv) { bv = lg[o]; best = o; }
        out[NN * OUTD + tnode] = (float)best;
    }
}

// ---------------------------------------------------------------------------
extern "C" void kernel_launch(void* const* d_in, const int* in_sizes, int n_in,
                              void* d_out, int out_size) {
    const float* features = (const float*)d_in[0];
    const float* boxes    = (const float*)d_in[1];
    const float* W_fc1    = (const float*)d_in[2];
    const float* b_fc1    = (const float*)d_in[3];
    const float* W_fc2    = (const float*)d_in[4];
    const float* b_fc2    = (const float*)d_in[5];
    const float* W1       = (const float*)d_in[6];
    const float* a_src1   = (const float*)d_in[7];
    const float* a_dst1   = (const float*)d_in[8];
    const float* b1       = (const float*)d_in[9];
    const float* W2       = (const float*)d_in[10];
    const float* a_src2   = (const float*)d_in[11];
    const float* a_dst2   = (const float*)d_in[12];
    const float* b2       = (const float*)d_in[13];
    const void*  img_h    = d_in[14];
    const void*  img_w    = d_in[15];
    float* out = (float*)d_out;

    k_mm<<<384, 256>>>(features, W_fc1, W1, boxes, img_h, img_w);
    k_rel<<<dim3(4, 32), 256>>>(boxes, W_fc1, b_fc1, W_fc2, b_fc2);
    k_topk_score<<<33, 1024>>>(W2, a_src1, a_dst1);
    k_gat1h<<<dim3(NN, HEADS), 128>>>(b1);
    k_g2<<<NN, 128>>>(a_src2, a_dst2);
    k_gat2<<<NN, 256>>>(b2, out, out_size);
}

// round 17
// speedup vs baseline: 1.2676x; 1.2676x over previous
#include <cuda_runtime.h>
#include <math.h>

#define NN    256
#define FEATD 1024
#define HIDR  256
#define HEADS 4
#define GCH   256
#define H1DIM 1024   // HEADS*GCH
#define OUTD  21
#define TOPK  3
#define E_TOT (NN*TOPK + NN)   // 1024 edges

// ---------------- scratch (device globals; no allocation allowed) ----------
__device__ __align__(16) float g_A[NN*HIDR];
__device__ __align__(16) float g_B[NN*HIDR];
__device__ __align__(16) float g_rel[NN*NN];
__device__ int   g_off[NN+1];
__device__ int   g_inc[E_TOT];
__device__ __align__(16) float g_h1[NN*H1DIM];
__device__ float g_ss1[NN*HEADS], g_ds1[NN*HEADS];
__device__ __align__(16) float g_h2[NN*OUTD];
__device__ float g_ss2[NN], g_ds2[NN];
__device__ __align__(16) float g_W2T[OUTD*H1DIM];   // W2 transposed [o][c]

// edge id -> source node (edges 0..767 are topk from row e/3; 768.. are loops)
__device__ __forceinline__ int edge_src(int e) {
    return (e < NN * TOPK) ? (e / TOPK) : (e - NN * TOPK);
}

// read a scalar that may have been serialized as int32 or float32
__device__ __forceinline__ float read_dim(const void* p) {
    int iv = *(const int*)p;
    if (iv > 0 && iv < 100000) return (float)iv;
    return *(const float*)p;
}

// ---------------- K1: combined GEMMs, 4-way split-K, 2 blocks/SM -----------
struct Acc44 { float a[4][4]; };

__global__ __launch_bounds__(512, 2)
void k_mm(const float* __restrict__ feat, const float* __restrict__ Wfc1,
          const float* __restrict__ W1, const float* __restrict__ boxes,
          const void* img_h, const void* img_w) {
    __shared__ float sbuf[6600];             // 4x tile sets (6400) / reduction (6528)
    int b = blockIdx.x;
    int t = threadIdx.x;
    int q = t >> 7, ht = t & 127;
    int tx4 = (ht & 15) * 4, ty4 = (ht >> 4) * 4;

    const float* W;
    float* dst;
    int row0, colL, ldw;
    bool gemm1 = (b >= 64);
    if (!gemm1) {
        int col0g = (b & 7) * 64;
        row0 = (b >> 3) * 32;
        ldw = HIDR;
        if (col0g < 256) { W = Wfc1;                       dst = g_A; colL = col0g; }
        else             { W = Wfc1 + (size_t)1024 * HIDR; dst = g_B; colL = col0g - 256; }
    } else {
        int i = b - 64;
        colL = (i & 15) * 64;
        row0 = (i >> 4) * 32;
        ldw = H1DIM;
        W = W1;
        dst = g_h1;
    }

    float* reg = sbuf + q * 1600;
    float (*sAT)[36] = (float (*)[36])reg;
    float (*sW)[64]  = (float (*)[64])(reg + 16 * 36);

    int arow = ht >> 2, akq = ht & 3;
    int wkr  = ht >> 3, wcq = ht & 7;
    int k0 = q * 256;                        // quarter of K=1024
    const float* Aptr = feat + (size_t)(row0 + arow) * FEATD + k0 + akq * 4;
    const float* Wptr = W + (size_t)(k0 + wkr) * ldw + colL + wcq * 8;

    Acc44 acc = {};
    float4 pa  = *(const float4*)Aptr;
    float4 pw0 = *(const float4*)Wptr;
    float4 pw1 = *(const float4*)(Wptr + 4);
#pragma unroll 1
    for (int kt = 0; kt < 16; kt++) {
        sAT[akq*4+0][arow] = pa.x;
        sAT[akq*4+1][arow] = pa.y;
        sAT[akq*4+2][arow] = pa.z;
        sAT[akq*4+3][arow] = pa.w;
        *(float4*)&sW[wkr][wcq*8]     = pw0;
        *(float4*)&sW[wkr][wcq*8 + 4] = pw1;
        __syncthreads();
        if (kt + 1 < 16) {
            const float* An = Aptr + (kt + 1) * 16;
            const float* Wn = Wptr + (size_t)(kt + 1) * 16 * ldw;
            pa  = *(const float4*)An;
            pw0 = *(const float4*)Wn;
            pw1 = *(const float4*)(Wn + 4);
        }
#pragma unroll
        for (int kk = 0; kk < 16; kk++) {
            float4 a = *(const float4*)&sAT[kk][ty4];
            float4 w = *(const float4*)&sW[kk][tx4];
            acc.a[0][0] += a.x * w.x; acc.a[0][1] += a.x * w.y; acc.a[0][2] += a.x * w.z; acc.a[0][3] += a.x * w.w;
            acc.a[1][0] += a.y * w.x; acc.a[1][1] += a.y * w.y; acc.a[1][2] += a.y * w.z; acc.a[1][3] += a.y * w.w;
            acc.a[2][0] += a.z * w.x; acc.a[2][1] += a.z * w.y; acc.a[2][2] += a.z * w.z; acc.a[2][3] += a.z * w.w;
            acc.a[3][0] += a.w * w.x; acc.a[3][1] += a.w * w.y; acc.a[3][2] += a.w * w.z; acc.a[3][3] += a.w * w.w;
        }
        __syncthreads();
    }

    // reduction: quarters 1..3 dump accs (stride 17 -> conflict-free), q0 sums
    if (q > 0) {
        float* rb = sbuf + (q - 1) * 2176 + ht * 17;
#pragma unroll
        for (int u = 0; u < 4; u++)
#pragma unroll
            for (int j = 0; j < 4; j++)
                rb[u * 4 + j] = acc.a[u][j];
    }
    __syncthreads();
    if (q == 0) {
#pragma unroll
        for (int r = 0; r < 3; r++) {
            float* rb = sbuf + r * 2176 + ht * 17;
#pragma unroll
            for (int u = 0; u < 4; u++)
#pragma unroll
                for (int j = 0; j < 4; j++)
                    acc.a[u][j] += rb[u * 4 + j];
        }
        if (gemm1) {
            float fw = read_dim(img_w), fh = read_dim(img_h);
#pragma unroll
            for (int u = 0; u < 4; u++) {
                int n = row0 + ty4 + u;
                float b0 = boxes[n*4+0] / fw, b1 = boxes[n*4+1] / fh;
                float b2 = boxes[n*4+2] / fw, b3 = boxes[n*4+3] / fh;
                float G[4] = { b0, b1, b2 - b0, b3 - b1 };
#pragma unroll
                for (int kk = 0; kk < 4; kk++) {
                    float4 w = *(const float4*)&W1[(size_t)(FEATD + kk) * H1DIM + colL + tx4];
                    acc.a[u][0] += G[kk] * w.x;
                    acc.a[u][1] += G[kk] * w.y;
                    acc.a[u][2] += G[kk] * w.z;
                    acc.a[u][3] += G[kk] * w.w;
                }
            }
        }
#pragma unroll
        for (int u = 0; u < 4; u++) {
            int r = row0 + ty4 + u;
            *(float4*)&dst[(size_t)r * ldw + colL + tx4] =
                make_float4(acc.a[u][0], acc.a[u][1], acc.a[u][2], acc.a[u][3]);
        }
    }
}

// ---------------- K2: rel[i,j] = relu(A[i]+B[j]+bias+geom@Wg) . W_fc2 + b2 -
// 256 threads (2 warps/SMSP -> FFMA-saturating). Thread = 1 i x 2 j.
__global__ __launch_bounds__(256)
void k_rel(const float* __restrict__ boxes,
           const float* __restrict__ Wfc1,
           const float* __restrict__ bfc1,
           const float* __restrict__ Wfc2,
           const float* __restrict__ bfc2) {
    __shared__ __align__(16) float sAb[8][HIDR];
    __shared__ __align__(16) float sBt[HIDR][68];
    __shared__ __align__(16) float4 sGeo[HIDR];
    __shared__ float sW2[HIDR];
    int t = threadIdx.x;                 // 256
    int il = t >> 5, lane = t & 31, jl = lane * 2;
    int i0 = blockIdx.y * 8, j0 = blockIdx.x * 64;
    const float* Wg = Wfc1 + (size_t)2 * FEATD * HIDR;
    for (int idx = t; idx < 8 * HIDR; idx += 256) {
        int i = idx >> 8, c = idx & 255;
        sAb[i][c] = g_A[(size_t)(i0 + i) * HIDR + c] + bfc1[c];
    }
    for (int idx = t; idx < 64 * HIDR; idx += 256) {
        int j = idx >> 8, c = idx & 255;
        sBt[c][j] = g_B[(size_t)(j0 + j) * HIDR + c];
    }
    for (int c = t; c < HIDR; c += 256) {
        sGeo[c] = make_float4(Wg[c], Wg[HIDR + c], Wg[2 * HIDR + c], Wg[3 * HIDR + c]);
        sW2[c] = Wfc2[c];
    }
    __syncthreads();
    int ig = i0 + il;
    float bi0 = boxes[ig*4+0], bi1 = boxes[ig*4+1], bi2 = boxes[ig*4+2], bi3 = boxes[ig*4+3];
    float4 G0, G1;
    {
        int ja = j0 + jl, jb = ja + 1;
        G0 = make_float4(fabsf(bi0 - boxes[ja*4+0]), fabsf(bi1 - boxes[ja*4+1]),
                         fabsf(bi2 - boxes[ja*4+2]), fabsf(bi3 - boxes[ja*4+3]));
        G1 = make_float4(fabsf(bi0 - boxes[jb*4+0]), fabsf(bi1 - boxes[jb*4+1]),
                         fabsf(bi2 - boxes[jb*4+2]), fabsf(bi3 - boxes[jb*4+3]));
    }
    float acc0 = 0.f, acc1 = 0.f;
#pragma unroll 4
    for (int c = 0; c < HIDR; c++) {
        float  a  = sAb[il][c];
        float4 wg = sGeo[c];
        float  w2 = sW2[c];
        float2 bv = *(const float2*)&sBt[c][jl];
        float v0 = a + bv.x + G0.x*wg.x + G0.y*wg.y + G0.z*wg.z + G0.w*wg.w;
        float v1 = a + bv.y + G1.x*wg.x + G1.y*wg.y + G1.z*wg.z + G1.w*wg.w;
        acc0 += fmaxf(v0, 0.f) * w2;
        acc1 += fmaxf(v1, 0.f) * w2;
    }
    float bb = bfc2[0];
    g_rel[(size_t)ig * NN + j0 + jl]     = acc0 + bb;
    g_rel[(size_t)ig * NN + j0 + jl + 1] = acc1 + bb;
}

// ---------------- K3: block 0 = topk + CSR + W2T; blocks 1..32 = score1 ----
__global__ void k_topk_score(const float* __restrict__ W2,
                             const float* __restrict__ a_src,
                             const float* __restrict__ a_dst) {
    int t = threadIdx.x;                 // 1024
    int lane = t & 31, w = t >> 5;
    if (blockIdx.x > 0) {
        // ---- score1: 8 nodes per block, 128 threads per node ----
        int n = (blockIdx.x - 1) * 8 + (t >> 7);
        int wt = t & 127;
        int hd = wt >> 5;
        float s = 0.f, d = 0.f;
        const float* hr = &g_h1[(size_t)n * H1DIM + hd * GCH];
        for (int c = lane; c < GCH; c += 32) {
            float hv = hr[c];
            s += hv * a_src[hd * GCH + c];
            d += hv * a_dst[hd * GCH + c];
        }
#pragma unroll
        for (int o = 16; o; o >>= 1) {
            s += __shfl_down_sync(0xffffffffu, s, o);
            d += __shfl_down_sync(0xffffffffu, d, o);
        }
        if (!lane) { g_ss1[n * HEADS + hd] = s; g_ds1[n * HEADS + hd] = d; }
        return;
    }
    // ---- block 0: topk + CSR + W2T ----
    __shared__ int sTop[NN * TOPK];
    __shared__ int M[32][NN];
    __shared__ int off[NN];
    for (int idx = t; idx < 32 * NN; idx += 1024) ((int*)M)[idx] = 0;
    for (int i = w; i < NN; i += 32) {
        float v[8];
#pragma unroll
        for (int q = 0; q < 8; q++) v[q] = g_rel[i * NN + q * 32 + lane];
#pragma unroll
        for (int sel = 0; sel < TOPK + 1; sel++) {
            float bv = -INFINITY; int bi = 0;
#pragma unroll
            for (int q = 0; q < 8; q++) {
                int idx = q * 32 + lane;
                if (v[q] > bv) { bv = v[q]; bi = idx; }
            }
#pragma unroll
            for (int o = 16; o; o >>= 1) {
                float ov = __shfl_down_sync(0xffffffffu, bv, o);
                int   oi = __shfl_down_sync(0xffffffffu, bi, o);
                if (ov > bv || (ov == bv && oi < bi)) { bv = ov; bi = oi; }
            }
            bi = __shfl_sync(0xffffffffu, bi, 0);
            if (sel > 0 && lane == 0) sTop[i * TOPK + sel - 1] = bi;
            if ((bi & 31) == lane) v[bi >> 5] = -INFINITY;
        }
    }
    for (int idx = t; idx < OUTD * H1DIM; idx += 1024) {
        int o = idx / H1DIM, c = idx - o * H1DIM;
        g_W2T[idx] = W2[c * OUTD + o];
    }
    __syncthreads();
    int e = t;
    int tg = (e < NN * TOPK) ? sTop[e] : (e - NN * TOPK);
    unsigned same = __match_any_sync(0xffffffffu, tg);
    int rank = __popc(same & ((1u << lane) - 1u));
    if (rank == 0) M[w][tg] = __popc(same);
    __syncthreads();
    if (t < NN) {
        int run = 0;
#pragma unroll
        for (int cc = 0; cc < 32; cc++) { int v = M[cc][t]; M[cc][t] = run; run += v; }
        off[t] = run;
    }
    __syncthreads();
    for (int s = 1; s < NN; s <<= 1) {
        int v = 0;
        if (t < NN && t >= s) v = off[t - s];
        __syncthreads();
        if (t < NN) off[t] += v;
        __syncthreads();
    }
    if (t < NN) {
        g_off[t + 1] = off[t];
        if (t == 0) g_off[0] = 0;
    }
    __syncthreads();
    int base = (tg == 0) ? 0 : off[tg - 1];
    g_inc[base + M[w][tg] + rank] = e;
}

// ---------------- K4: fused GAT1 agg (2 edge-slices) + gemm2 + scores2 -----
__global__ __launch_bounds__(512)
void k_gat1f(const float* __restrict__ b1,
             const float* __restrict__ a_src2,
             const float* __restrict__ a_dst2) {
    int tnode = blockIdx.x, tid = threadIdx.x;   // 512 threads
    int w = tid >> 5, lane = tid & 31;
    int off = g_off[tnode], cnt = g_off[tnode + 1] - off;
    __shared__ int   sSrc[E_TOT];
    __shared__ float al[E_TOT * HEADS];
    __shared__ __align__(16) float sX[H1DIM];
    __shared__ __align__(16) float sXp[H1DIM];   // slice-1 partials
    __shared__ float lg[OUTD];
    for (int k = tid; k < cnt; k += 512) sSrc[k] = edge_src(g_inc[off + k]);
    __syncthreads();
    for (int idx = tid; idx < cnt * HEADS; idx += 512) {
        int k = idx >> 2, hd = idx & 3;
        float x = g_ss1[sSrc[k] * HEADS + hd] + g_ds1[tnode * HEADS + hd];
        al[idx] = (x >= 0.f) ? x : 0.2f * x;   // leaky_relu 0.2
    }
    __syncthreads();
    // warp-parallel softmax per head (warps 0..3)
    if (w < HEADS) {
        float m = -INFINITY;
        for (int k = lane; k < cnt; k += 32) m = fmaxf(m, al[k * HEADS + w]);
#pragma unroll
        for (int o = 16; o; o >>= 1) m = fmaxf(m, __shfl_xor_sync(0xffffffffu, m, o));
        float s = 0.f;
        for (int k = lane; k < cnt; k += 32) {
            float p = expf(al[k * HEADS + w] - m);
            al[k * HEADS + w] = p;
            s += p;
        }
#pragma unroll
        for (int o = 16; o; o >>= 1) s += __shfl_xor_sync(0xffffffffu, s, o);
        float inv = 1.f / s;
        for (int k = lane; k < cnt; k += 32) al[k * HEADS + w] *= inv;
    }
    __syncthreads();
    // aggregation: 2 edge-slices x 256 output-threads; unroll-by-4 per slice
    {
        int slice = tid >> 8, ot = tid & 255;
        int o4 = ot * 4;
        int hd = o4 >> 8;
        float ax = 0.f, ay = 0.f, az = 0.f, aw = 0.f;
        int k = slice;
        for (; k + 6 < cnt; k += 8) {
            float a0 = al[(k+0) * HEADS + hd];
            float a1 = al[(k+2) * HEADS + hd];
            float a2 = al[(k+4) * HEADS + hd];
            float a3 = al[(k+6) * HEADS + hd];
            const float4 h0 = *(const float4*)&g_h1[(size_t)sSrc[k+0] * H1DIM + o4];
            const float4 h1 = *(const float4*)&g_h1[(size_t)sSrc[k+2] * H1DIM + o4];
            const float4 h2 = *(const float4*)&g_h1[(size_t)sSrc[k+4] * H1DIM + o4];
            const float4 h3 = *(const float4*)&g_h1[(size_t)sSrc[k+6] * H1DIM + o4];
            ax += a0*h0.x + a1*h1.x + a2*h2.x + a3*h3.x;
            ay += a0*h0.y + a1*h1.y + a2*h2.y + a3*h3.y;
            az += a0*h0.z + a1*h1.z + a2*h2.z + a3*h3.z;
            aw += a0*h0.w + a1*h1.w + a2*h2.w + a3*h3.w;
        }
        for (; k < cnt; k += 2) {
            float a = al[k * HEADS + hd];
            const float4 h = *(const float4*)&g_h1[(size_t)sSrc[k] * H1DIM + o4];
            ax += a * h.x; ay += a * h.y; az += a * h.z; aw += a * h.w;
        }
        if (slice == 1) {
            *(float4*)&sXp[o4] = make_float4(ax, ay, az, aw);
        }
        __syncthreads();
        if (slice == 0) {
            float4 p = *(const float4*)&sXp[o4];
            float4 bb = *(const float4*)&b1[o4];
            *(float4*)&sX[o4] = make_float4(
                fmaxf(ax + p.x + bb.x, 0.f), fmaxf(ay + p.y + bb.y, 0.f),
                fmaxf(az + p.z + bb.z, 0.f), fmaxf(aw + p.w + bb.w, 0.f));
        }
    }
    __syncthreads();
    // gemm2: h2 row = sX @ W2T, warp per output (16 warps)
    for (int o = w; o < OUTD; o += 16) {
        const float* wr = &g_W2T[o * H1DIM];
        float s = 0.f;
        for (int c = lane * 4; c < H1DIM; c += 128) {
            float4 xv = *(const float4*)&sX[c];
            float4 wv = *(const float4*)&wr[c];
            s += xv.x * wv.x + xv.y * wv.y + xv.z * wv.z + xv.w * wv.w;
        }
#pragma unroll
        for (int o2 = 16; o2; o2 >>= 1) s += __shfl_down_sync(0xffffffffu, s, o2);
        if (!lane) { g_h2[tnode * OUTD + o] = s; lg[o] = s; }
    }
    __syncthreads();
    if (tid == 0) {
        float s = 0.f, d = 0.f;
        for (int oo = 0; oo < OUTD; oo++) {
            s += lg[oo] * a_src2[oo];
            d += lg[oo] * a_dst2[oo];
        }
        g_ss2[tnode] = s; g_ds2[tnode] = d;
    }
}

// ---------------- K5: GAT2 edge-sliced aggregate -> logits + labels --------
__global__ void k_gat2(const float* __restrict__ b2, float* __restrict__ out,
                       int out_size) {
    int tnode = blockIdx.x, tid = threadIdx.x;   // 256 threads
    int off = g_off[tnode], cnt = g_off[tnode + 1] - off;
    __shared__ int   sSrc[E_TOT];
    __shared__ float al[E_TOT];
    __shared__ float red[2];            // m, inv_sum
    __shared__ float partial[8][32];
    __shared__ float lg[OUTD];
    for (int k = tid; k < cnt; k += 256) {
        int sn = edge_src(g_inc[off + k]);
        sSrc[k] = sn;
        float x = g_ss2[sn] + g_ds2[tnode];
        al[k] = (x >= 0.f) ? x : 0.2f * x;
    }
    __syncthreads();
    // warp 0: max + sum
    if (tid < 32) {
        float m = -INFINITY;
        for (int k = tid; k < cnt; k += 32) m = fmaxf(m, al[k]);
#pragma unroll
        for (int o = 16; o; o >>= 1) m = fmaxf(m, __shfl_xor_sync(0xffffffffu, m, o));
        float s = 0.f;
        for (int k = tid; k < cnt; k += 32) s += expf(al[k] - m);
#pragma unroll
        for (int o = 16; o; o >>= 1) s += __shfl_xor_sync(0xffffffffu, s, o);
        if (tid == 0) { red[0] = m; red[1] = 1.f / s; }
    }
    __syncthreads();
    float m = red[0], inv = red[1];
    for (int k = tid; k < cnt; k += 256) al[k] = expf(al[k] - m) * inv;
    __syncthreads();
    // edge-sliced aggregation: 8 slices x 32 lanes (o < 21 active)
    {
        int es = tid >> 5, o = tid & 31;
        if (o < OUTD) {
            float acc = 0.f;
            for (int k = es; k < cnt; k += 8)
                acc += al[k] * g_h2[sSrc[k] * OUTD + o];
            partial[es][o] = acc;
        }
    }
    __syncthreads();
    if (tid < OUTD) {
        float v = b2[tid];
#pragma unroll
        for (int es = 0; es < 8; es++) v += partial[es][tid];
        lg[tid] = v;
        out[tnode * OUTD + tid] = v;
    }
    __syncthreads();
    if (tid == 0 && out_size >= NN * OUTD + NN) {
        int best = 0;
        float bv = lg[0];
        for (int o = 1; o < OUTD; o++)
            if (lg[o] > bv) { bv = lg[o]; best = o; }
        out[NN * OUTD + tnode] = (float)best;
    }
}

// ---------------------------------------------------------------------------
extern "C" void kernel_launch(void* const* d_in, const int* in_sizes, int n_in,
                              void* d_out, int out_size) {
    const float* features = (const float*)d_in[0];
    const float* boxes    = (const float*)d_in[1];
    const float* W_fc1    = (const float*)d_in[2];
    const float* b_fc1    = (const float*)d_in[3];
    const float* W_fc2    = (const float*)d_in[4];
    const float* b_fc2    = (const float*)d_in[5];
    const float* W1       = (const float*)d_in[6];
    const float* a_src1   = (const float*)d_in[7];
    const float* a_dst1   = (const float*)d_in[8];
    const float* b1       = (const float*)d_in[9];
    const float* W2       = (const float*)d_in[10];
    const float* a_src2   = (const float*)d_in[11];
    const float* a_dst2   = (const float*)d_in[12];
    const float* b2       = (const float*)d_in[13];
    const void*  img_h    = d_in[14];
    const void*  img_w    = d_in[15];
    float* out = (float*)d_out;

    k_mm<<<192, 512>>>(features, W_fc1, W1, boxes, img_h, img_w);
    k_rel<<<dim3(4, 32), 256>>>(boxes, W_fc1, b_fc1, W_fc2, b_fc2);
    k_topk_score<<<33, 1024>>>(W2, a_src1, a_dst1);
    k_gat1f<<<NN, 512>>>(b1, a_src2, a_dst2);
    k_gat2<<<NN, 256>>>(b2, out, out_size);
}